// round 14
// baseline (speedup 1.0000x reference)
#include <cuda_runtime.h>
#include <cuda_fp16.h>
#include <math.h>

#define NCTA 128
#define NTH  512
#define Bsz  256
#define Tlen 1024
#define Hdim 256
#define K2n  128   // Hdim/2 k-pairs (f32x2 lanes)
#define KQn  64    // Hdim/4 k-quads
#define KQPT 16    // KQn / 4 k-split groups

// Persistent state, exchanged through L2 in fp16 (double-buffered by parity).
// uint2 layout: [kq][b] packs {half2(h[4kq],h[4kq+1]), half2(h[4kq+2],h[4kq+3])}.
// Parity p holds the pair (h0(t), h1(t-1)) for t with t&1 == p.
__device__ uint2 g_h0h[2][KQn * Bsz];
__device__ uint2 g_h1h[2][KQn * Bsz];
__device__ float g_xT[Tlen * Bsz];   // x transposed: [t][b]
__device__ unsigned g_cnt  = 0;      // single barrier line
__device__ unsigned g_done = 0;      // end-of-kernel reset rendezvous

union F2U { float2 f; unsigned long long u; };

__device__ __forceinline__ unsigned long long pack2(float a, float b) {
    F2U v; v.f.x = a; v.f.y = b; return v.u;
}
// half2 (as u32) -> float2 packed in u64
__device__ __forceinline__ unsigned long long h2f2(unsigned int u) {
    __half2 h = *reinterpret_cast<__half2*>(&u);
    F2U v; v.f = __half22float2(h); return v.u;
}
// Blackwell packed fp32x2 FMA: 2 exact fp32 MACs per instruction.
__device__ __forceinline__ unsigned long long ffma2(unsigned long long a,
                                                    unsigned long long b,
                                                    unsigned long long c) {
    unsigned long long d;
    asm("fma.rn.f32x2 %0, %1, %2, %3;" : "=l"(d) : "l"(a), "l"(b), "l"(c));
    return d;
}
__device__ __forceinline__ float redsum(unsigned long long a) {
    F2U v; v.u = a; return v.f.x + v.f.y;
}
__device__ __forceinline__ float sigf(float x) {
    return __fdividef(1.0f, 1.0f + __expf(-x));
}
__device__ __forceinline__ float tanhf_(float x) {
    return fmaf(2.0f, sigf(2.0f * x), -1.0f);
}

// Split-phase grid barrier (NCTA co-resident CTAs, 1/SM).
__device__ __forceinline__ void bar_arrive(unsigned* c) {
    __syncthreads();                       // CTA's stores done
    if (threadIdx.x == 0) {
        asm volatile("red.release.gpu.global.add.u32 [%0], %1;"
                     :: "l"(c), "r"(1u) : "memory");
    }
}
__device__ __forceinline__ void bar_wait(unsigned* c, unsigned target) {
    if (threadIdx.x == 0) {
        unsigned v;
        do {
            asm volatile("ld.acquire.gpu.u32 %0, [%1];" : "=r"(v) : "l"(c));
        } while (v < target);
    }
    __syncthreads();
}

// ---- layer-0 matvec slice: partials into sRed rows [16..32) ----
__device__ __forceinline__ void mv_l0(const uint2* __restrict__ hp,
                                      const ulonglong2* __restrict__ sW,
                                      float4* __restrict__ sRed,
                                      int b2, int ks, int kq0) {
    unsigned long long aA[4][2], aB[4][2];
    #pragma unroll
    for (int q = 0; q < 4; ++q) { aA[q][0]=0ull; aA[q][1]=0ull; aB[q][0]=0ull; aB[q][1]=0ull; }
    #pragma unroll 8
    for (int i = 0; i < KQPT; ++i) {
        int kq = kq0 + i;
        uint2 rA = __ldcg(hp + kq * Bsz + b2);          // LDG.64: 4 fp16 units
        uint2 rB = __ldcg(hp + kq * Bsz + b2 + 128);
        unsigned long long hAx = h2f2(rA.x), hAy = h2f2(rA.y);
        unsigned long long hBx = h2f2(rB.x), hBy = h2f2(rB.y);
        int k2 = 2 * kq;
        #pragma unroll
        for (int q = 0; q < 4; ++q) {
            ulonglong2 w0 = sW[k2 * 4 + q];             // broadcast LDS.128
            ulonglong2 w1 = sW[(k2 + 1) * 4 + q];
            aA[q][0] = ffma2(hAx, w0.x, aA[q][0]);
            aA[q][1] = ffma2(hAx, w0.y, aA[q][1]);
            aB[q][0] = ffma2(hBx, w0.x, aB[q][0]);
            aB[q][1] = ffma2(hBx, w0.y, aB[q][1]);
            aA[q][0] = ffma2(hAy, w1.x, aA[q][0]);
            aA[q][1] = ffma2(hAy, w1.y, aA[q][1]);
            aB[q][0] = ffma2(hBy, w1.x, aB[q][0]);
            aB[q][1] = ffma2(hBy, w1.y, aB[q][1]);
        }
    }
    #pragma unroll
    for (int jj = 0; jj < 2; ++jj) {
        sRed[(16 + ks*4 + jj*2 + 0)*128 + b2] =
            make_float4(redsum(aA[0][jj]), redsum(aA[1][jj]),
                        redsum(aA[2][jj]), redsum(aA[3][jj]));
        sRed[(16 + ks*4 + jj*2 + 1)*128 + b2] =
            make_float4(redsum(aB[0][jj]), redsum(aB[1][jj]),
                        redsum(aB[2][jj]), redsum(aB[3][jj]));
    }
}

// ---- layer-1 matvec slice (two inputs): partials into sRed rows [0..16) ----
__device__ __forceinline__ void mv_l1(const uint2* __restrict__ ha,
                                      const uint2* __restrict__ hb,
                                      const ulonglong2* __restrict__ sWi,
                                      const ulonglong2* __restrict__ sWh,
                                      float4* __restrict__ sRed,
                                      int b2, int ks, int kq0) {
    unsigned long long aA[4][2], aB[4][2];
    #pragma unroll
    for (int q = 0; q < 4; ++q) { aA[q][0]=0ull; aA[q][1]=0ull; aB[q][0]=0ull; aB[q][1]=0ull; }
    #pragma unroll 4
    for (int i = 0; i < KQPT; ++i) {
        int kq = kq0 + i;
        uint2 raA = __ldcg(ha + kq * Bsz + b2);
        uint2 raB = __ldcg(ha + kq * Bsz + b2 + 128);
        uint2 rbA = __ldcg(hb + kq * Bsz + b2);
        uint2 rbB = __ldcg(hb + kq * Bsz + b2 + 128);
        unsigned long long vaAx = h2f2(raA.x), vaAy = h2f2(raA.y);
        unsigned long long vaBx = h2f2(raB.x), vaBy = h2f2(raB.y);
        unsigned long long vbAx = h2f2(rbA.x), vbAy = h2f2(rbA.y);
        unsigned long long vbBx = h2f2(rbB.x), vbBy = h2f2(rbB.y);
        int k2 = 2 * kq;
        #pragma unroll
        for (int q = 0; q < 4; ++q) {
            ulonglong2 wi0 = sWi[k2 * 4 + q];
            ulonglong2 wi1 = sWi[(k2 + 1) * 4 + q];
            ulonglong2 wh0 = sWh[k2 * 4 + q];
            ulonglong2 wh1 = sWh[(k2 + 1) * 4 + q];
            aA[q][0] = ffma2(vaAx, wi0.x, aA[q][0]);
            aA[q][1] = ffma2(vaAx, wi0.y, aA[q][1]);
            aB[q][0] = ffma2(vaBx, wi0.x, aB[q][0]);
            aB[q][1] = ffma2(vaBx, wi0.y, aB[q][1]);
            aA[q][0] = ffma2(vaAy, wi1.x, aA[q][0]);
            aA[q][1] = ffma2(vaAy, wi1.y, aA[q][1]);
            aB[q][0] = ffma2(vaBy, wi1.x, aB[q][0]);
            aB[q][1] = ffma2(vaBy, wi1.y, aB[q][1]);
            aA[q][0] = ffma2(vbAx, wh0.x, aA[q][0]);
            aA[q][1] = ffma2(vbAx, wh0.y, aA[q][1]);
            aB[q][0] = ffma2(vbBx, wh0.x, aB[q][0]);
            aB[q][1] = ffma2(vbBx, wh0.y, aB[q][1]);
            aA[q][0] = ffma2(vbAy, wh1.x, aA[q][0]);
            aA[q][1] = ffma2(vbAy, wh1.y, aA[q][1]);
            aB[q][0] = ffma2(vbBy, wh1.x, aB[q][0]);
            aB[q][1] = ffma2(vbBy, wh1.y, aB[q][1]);
        }
    }
    #pragma unroll
    for (int jj = 0; jj < 2; ++jj) {
        sRed[(ks*4 + jj*2 + 0)*128 + b2] =
            make_float4(redsum(aA[0][jj]), redsum(aA[1][jj]),
                        redsum(aA[2][jj]), redsum(aA[3][jj]));
        sRed[(ks*4 + jj*2 + 1)*128 + b2] =
            make_float4(redsum(aB[0][jj]), redsum(aB[1][jj]),
                        redsum(aB[2][jj]), redsum(aB[3][jj]));
    }
}

// gather this thread's (j,m) gate sums from the 4 k-group partials
__device__ __forceinline__ float4 red_gather(const float4* __restrict__ sRed,
                                             int base, int ks, int b2) {
    float4 s = sRed[(base + 0*4 + ks)*128 + b2];
    #pragma unroll
    for (int g = 1; g < 4; ++g) {
        float4 v = sRed[(base + g*4 + ks)*128 + b2];
        s.x += v.x; s.y += v.y; s.z += v.z; s.w += v.w;
    }
    return s;
}

__global__ void __launch_bounds__(NTH, 1)
lstm_fused(const float* __restrict__ x,
           const float* __restrict__ Wih0, const float* __restrict__ Whh0,
           const float* __restrict__ bih0, const float* __restrict__ bhh0,
           const float* __restrict__ Wih1, const float* __restrict__ Whh1,
           const float* __restrict__ bih1, const float* __restrict__ bhh1,
           const float* __restrict__ Wlin, const float* __restrict__ blin,
           float* __restrict__ out)
{
    __shared__ ulonglong2 sW0 [K2n * 4];   // 8 KB each, pair-packed [k2*4+q]
    __shared__ ulonglong2 sW1i[K2n * 4];
    __shared__ ulonglong2 sW1h[K2n * 4];
    __shared__ float4 sRed[32 * 128];      // 64 KB: rows [0,16) L1, [16,32) L0
    __shared__ float sWx[8], sB0[8], sB1[8];
    __shared__ float4 sW4[KQn];            // Wlin as quads
    __shared__ float sOut[4];

    const int tid = threadIdx.x;
    const int b2  = tid & 127;
    const int ks  = tid >> 7;              // 0..3 (warp-uniform)
    const int cta = blockIdx.x;
    const int u0  = 2 * cta;
    const int jmu = ks >> 1;               // unit-in-pair this thread activates
    const int mmu = ks & 1;                // batch-half this thread activates
    const int bown = b2 + mmu * 128;       // owned batch index
    const int kq0 = ks * KQPT;
    // activation write target: unit u = u0 + jmu in quad/half layout
    const int widx = (((u0 + jmu) >> 2) * Bsz + bown) * 4 + ((u0 + jmu) & 3);
    // output-gather role (tid < 128): quad okq, batch obb
    const int okq = tid & 63;
    const int obb = u0 + ((tid >> 6) & 1);

    // ---- one-time staging ----
    for (int i = cta * NTH + tid; i < Bsz * Tlen; i += NCTA * NTH) {
        int b = i >> 10, t = i & (Tlen - 1);
        g_xT[t * Bsz + b] = x[i];
    }
    for (int e = tid; e < K2n * 4; e += NTH) {
        int k2 = e >> 2, q = e & 3;
        int base = (q * Hdim + u0) * Hdim + 2 * k2;
        sW0[e]  = make_ulonglong2(pack2(Whh0[base],        Whh0[base + 1]),
                                  pack2(Whh0[base + Hdim], Whh0[base + Hdim + 1]));
        sW1i[e] = make_ulonglong2(pack2(Wih1[base],        Wih1[base + 1]),
                                  pack2(Wih1[base + Hdim], Wih1[base + Hdim + 1]));
        sW1h[e] = make_ulonglong2(pack2(Whh1[base],        Whh1[base + 1]),
                                  pack2(Whh1[base + Hdim], Whh1[base + Hdim + 1]));
    }
    if (tid < 8) {
        int q = tid >> 1, j = tid & 1;
        int g = q * Hdim + u0 + j;
        sWx[tid] = Wih0[g];                // input dim == 1
        sB0[tid] = bih0[g] + bhh0[g];
        sB1[tid] = bih1[g] + bhh1[g];
    }
    if (tid < KQn) sW4[tid] = ((const float4*)Wlin)[tid];
    const float bl = __ldg(blin);

    if (tid < 128)                          // h1(-1) = 0 (parity-0), CTA's slice
        g_h1h[0][cta * 128 + tid] = make_uint2(0u, 0u);
    float c0 = 0.f, c1 = 0.f;               // distributed cell state (fp32)

    // barrier 1: staging + zeros visible
    bar_arrive(&g_cnt);
    bar_wait(&g_cnt, 1u * NCTA);

    // ---- prologue: h0(0) from zero state (no matvec needed) ----
    {
        float xv = g_xT[0 * Bsz + bown];
        float gi = fmaf(sWx[0*2 + jmu], xv, sB0[0*2 + jmu]);
        float gg = fmaf(sWx[2*2 + jmu], xv, sB0[2*2 + jmu]);
        float go = fmaf(sWx[3*2 + jmu], xv, sB0[3*2 + jmu]);
        float cn = sigf(gi) * tanhf_(gg);   // f-gate * 0 drops
        c0 = cn;
        ((__half*)g_h0h[0])[widx] = __float2half_rn(sigf(go) * tanhf_(cn));
    }
    bar_arrive(&g_cnt);
    bar_wait(&g_cnt, 2u * NCTA);            // h0(0), h1(-1) all visible

    for (int t = 0; t < Tlen; ++t) {
        const int p = t & 1, nx = p ^ 1;

        // prefetch output operand for step t-1: h1(t-1) lives at parity p
        uint2 hv_pref = make_uint2(0u, 0u);
        if (tid < 128) hv_pref = __ldcg(&g_h1h[p][okq * Bsz + obb]);

        // ---- both matvecs, back-to-back ----
        mv_l1(g_h0h[p], g_h1h[p], sW1i, sW1h, sRed, b2, ks, kq0);
        if (t < Tlen - 1)
            mv_l0(g_h0h[p], sW0, sRed, b2, ks, kq0);
        __syncthreads();

        // ---- merged activations ----
        {   // layer 1: h1(t)
            float4 s = red_gather(sRed, 0, ks, b2);
            float gi = s.x + sB1[0*2 + jmu];
            float gf = s.y + sB1[1*2 + jmu];
            float gg = s.z + sB1[2*2 + jmu];
            float go = s.w + sB1[3*2 + jmu];
            float cn = sigf(gf) * c1 + sigf(gi) * tanhf_(gg);
            c1 = cn;
            ((__half*)g_h1h[nx])[widx] = __float2half_rn(sigf(go) * tanhf_(cn));
        }
        if (t < Tlen - 1) {  // layer 0: h0(t+1)
            float4 s = red_gather(sRed, 16, ks, b2);
            float xv = g_xT[(t + 1) * Bsz + bown];
            float gi = s.x + fmaf(sWx[0*2 + jmu], xv, sB0[0*2 + jmu]);
            float gf = s.y + fmaf(sWx[1*2 + jmu], xv, sB0[1*2 + jmu]);
            float gg = s.z + fmaf(sWx[2*2 + jmu], xv, sB0[2*2 + jmu]);
            float go = s.w + fmaf(sWx[3*2 + jmu], xv, sB0[3*2 + jmu]);
            float cn = sigf(gf) * c0 + sigf(gi) * tanhf_(gg);
            c0 = cn;
            ((__half*)g_h0h[nx])[widx] = __float2half_rn(sigf(go) * tanhf_(cn));
        }

        // ---- arrive FIRST; output(t-1) executes inside the wait shadow ----
        bar_arrive(&g_cnt);

        if (t >= 1) {
            if (tid < 128) {
                F2U lo, hi;
                lo.u = h2f2(hv_pref.x);
                hi.u = h2f2(hv_pref.y);
                float4 wl = sW4[okq];
                float part = lo.f.x * wl.x + lo.f.y * wl.y
                           + hi.f.x * wl.z + hi.f.y * wl.w;
                #pragma unroll
                for (int off = 16; off > 0; off >>= 1)
                    part += __shfl_down_sync(0xffffffffu, part, off);
                if ((tid & 31) == 0) sOut[tid >> 5] = part;
            }
            __syncthreads();
            if (tid == 0) {
                out[(u0 + 0) * Tlen + (t - 1)] = sOut[0] + sOut[1] + bl;
                out[(u0 + 1) * Tlen + (t - 1)] = sOut[2] + sOut[3] + bl;
            }
        }

        bar_wait(&g_cnt, (unsigned)(t + 3) * NCTA);
    }

    // ---- final output(1023): h1(1023) at parity 0 ----
    {
        if (tid < 128) {
            uint2 hv = __ldcg(&g_h1h[0][okq * Bsz + obb]);
            F2U lo, hi;
            lo.u = h2f2(hv.x);
            hi.u = h2f2(hv.y);
            float4 wl = sW4[okq];
            float part = lo.f.x * wl.x + lo.f.y * wl.y
                       + hi.f.x * wl.z + hi.f.y * wl.w;
            #pragma unroll
            for (int off = 16; off > 0; off >>= 1)
                part += __shfl_down_sync(0xffffffffu, part, off);
            if ((tid & 31) == 0) sOut[tid >> 5] = part;
        }
        __syncthreads();
        if (tid == 0) {
            out[(u0 + 0) * Tlen + (Tlen - 1)] = sOut[0] + sOut[1] + bl;
            out[(u0 + 1) * Tlen + (Tlen - 1)] = sOut[2] + sOut[3] + bl;
        }
    }

    // reset counters for next launch
    __syncthreads();
    if (tid == 0) {
        __threadfence();
        unsigned old = atomicAdd(&g_done, 1u);
        if (old == NCTA - 1) {
            atomicExch(&g_cnt, 0u);
            atomicExch(&g_done, 0u);
        }
    }
}

extern "C" void kernel_launch(void* const* d_in, const int* in_sizes, int n_in,
                              void* d_out, int out_size) {
    (void)in_sizes; (void)n_in; (void)out_size;
    lstm_fused<<<NCTA, NTH>>>(
        (const float*)d_in[0],
        (const float*)d_in[1], (const float*)d_in[2],
        (const float*)d_in[3], (const float*)d_in[4],
        (const float*)d_in[5], (const float*)d_in[6],
        (const float*)d_in[7], (const float*)d_in[8],
        (const float*)d_in[9], (const float*)d_in[10],
        (float*)d_out);
}

// round 15
// speedup vs baseline: 2.5531x; 2.5531x over previous
#include <cuda_runtime.h>
#include <cuda_fp16.h>
#include <math.h>

#define NCTA 128
#define NTH  512
#define Bsz  256
#define Tlen 1024
#define Hdim 256

#define LDA 264                       // padded halfs per smem row (528 B)
#define ROWB 528                      // row stride bytes (A and B tiles)
#define BS_WARP (16 * ROWB)           // 8448 B per-warp B bounce buffer
#define OFF_A0 0
#define OFF_A1 8448
#define OFF_BS 16896
#define DYN_SMEM (OFF_BS + 16 * BS_WARP)   // 152064 B

// Persistent h state, fp16, layout [b][k] (k contiguous), double-buffered.
// Parity p holds (h0(t), h1(t-1)) for t with t&1 == p.
__device__ __half g_h0[2][Bsz * Hdim];
__device__ __half g_h1[2][Bsz * Hdim];
__device__ float g_xT[Tlen * Bsz];    // x transposed [t][b]
__device__ unsigned g_cnt = 0, g_done = 0;

__device__ __forceinline__ float sigf(float x) {
    return __fdividef(1.0f, 1.0f + __expf(-x));
}
__device__ __forceinline__ float tanhf_(float x) {
    return fmaf(2.0f, sigf(2.0f * x), -1.0f);
}
__device__ __forceinline__ unsigned smem_u32(const void* p) {
    unsigned a;
    asm("{ .reg .u64 t; cvta.to.shared.u64 t, %1; cvt.u32.u64 %0, t; }"
        : "=r"(a) : "l"(p));
    return a;
}
__device__ __forceinline__ void ldm_x4(unsigned addr, unsigned& r0, unsigned& r1,
                                       unsigned& r2, unsigned& r3) {
    asm volatile("ldmatrix.sync.aligned.m8n8.x4.shared.b16 {%0,%1,%2,%3}, [%4];"
                 : "=r"(r0), "=r"(r1), "=r"(r2), "=r"(r3) : "r"(addr) : "memory");
}
__device__ __forceinline__ void mma16816(float* d, unsigned a0, unsigned a1,
                                         unsigned a2, unsigned a3,
                                         unsigned b0, unsigned b1) {
    asm volatile("mma.sync.aligned.m16n8k16.row.col.f32.f16.f16.f32 "
                 "{%0,%1,%2,%3}, {%4,%5,%6,%7}, {%8,%9}, {%0,%1,%2,%3};"
                 : "+f"(d[0]), "+f"(d[1]), "+f"(d[2]), "+f"(d[3])
                 : "r"(a0), "r"(a1), "r"(a2), "r"(a3), "r"(b0), "r"(b1));
}

// Split-phase grid barrier (NCTA co-resident CTAs, 1/SM).
__device__ __forceinline__ void bar_arrive(unsigned* c) {
    __syncthreads();
    if (threadIdx.x == 0) {
        asm volatile("red.release.gpu.global.add.u32 [%0], %1;"
                     :: "l"(c), "r"(1u) : "memory");
    }
}
__device__ __forceinline__ void bar_wait(unsigned* c, unsigned target) {
    if (threadIdx.x == 0) {
        unsigned v;
        do {
            asm volatile("ld.acquire.gpu.u32 %0, [%1];" : "=r"(v) : "l"(c));
        } while (v < target);
    }
    __syncthreads();
}

__global__ void __launch_bounds__(NTH, 1)
lstm_mma(const float* __restrict__ x,
         const float* __restrict__ Wih0, const float* __restrict__ Whh0,
         const float* __restrict__ bih0, const float* __restrict__ bhh0,
         const float* __restrict__ Wih1, const float* __restrict__ Whh1,
         const float* __restrict__ bih1, const float* __restrict__ bhh1,
         const float* __restrict__ Wlin, const float* __restrict__ blin,
         float* __restrict__ out)
{
    extern __shared__ char dsm[];
    __half* sA0 = (__half*)(dsm + OFF_A0);   // [16 rows x 256 k] rows: 8 Whh0, 8 Wih1
    __half* sA1 = (__half*)(dsm + OFF_A1);   // rows: 8 Whh1, 8 zeros
    char*   BsP = dsm + OFF_BS;              // 16 warps x [16 n x 256 k] fp16

    __shared__ float  sG[16 * 260];          // gates: rows 0-7 L0, 8-15 L1
    __shared__ float4 sW4[64];               // Wlin quads
    __shared__ float  sWx[8], sB0[8], sB1[8];
    __shared__ float  sOut[4];

    const int tid = threadIdx.x, lane = tid & 31, warp = tid >> 5;
    const int cta = blockIdx.x, u0 = 2 * cta;
    const int jmu = tid >> 8, bown = tid & 255;     // activation role

    const unsigned sbase = smem_u32(dsm);
    const unsigned a0_u = sbase + OFF_A0;
    const unsigned a1_u = sbase + OFF_A1;
    const unsigned bs_u = sbase + OFF_BS + warp * BS_WARP;
    char* BsW = BsP + warp * BS_WARP;

    // per-lane ldmatrix row/k-half selectors
    const int a_row = (lane < 16) ? lane : lane - 16;
    const int a_kh  = (lane < 16) ? 0 : 8;
    const int b_row = (lane & 7) + ((lane >= 16) ? 8 : 0);
    const int b_kh  = (lane & 8) ? 8 : 0;

    // ---- one-time staging ----
    for (int i = cta * NTH + tid; i < Bsz * Tlen; i += NCTA * NTH) {
        int b = i >> 10, t = i & (Tlen - 1);
        g_xT[t * Bsz + b] = x[i];
    }
    for (int e = tid; e < 16 * 256; e += NTH) {
        int r = e >> 8, k = e & 255;
        int rr = (r < 8) ? r : r - 8;
        int q = rr >> 1, j = rr & 1;
        int gidx = (q * Hdim + u0 + j) * Hdim + k;
        sA0[r * LDA + k] = __float2half((r < 8) ? Whh0[gidx] : Wih1[gidx]);
        sA1[r * LDA + k] = __float2half((r < 8) ? Whh1[gidx] : 0.0f);
    }
    if (tid < 8) {
        int q = tid >> 1, j = tid & 1;
        int g = q * Hdim + u0 + j;
        sWx[tid] = Wih0[g];
        sB0[tid] = bih0[g] + bhh0[g];
        sB1[tid] = bih1[g] + bhh1[g];
    }
    if (tid < 64) sW4[tid] = ((const float4*)Wlin)[tid];
    const float bl = __ldg(blin);

    g_h1[0][bown * Hdim + u0 + jmu] = __float2half(0.0f);   // h1(-1) = 0
    float c0 = 0.f, c1 = 0.f;

    bar_arrive(&g_cnt); bar_wait(&g_cnt, 1u * NCTA);

    // ---- prologue: h0(0) from zero state ----
    {
        float xv = g_xT[bown];
        float gi = fmaf(sWx[0*2 + jmu], xv, sB0[0*2 + jmu]);
        float gg = fmaf(sWx[2*2 + jmu], xv, sB0[2*2 + jmu]);
        float go = fmaf(sWx[3*2 + jmu], xv, sB0[3*2 + jmu]);
        float cn = sigf(gi) * tanhf_(gg);
        c0 = cn;
        g_h0[0][bown * Hdim + u0 + jmu] = __float2half(sigf(go) * tanhf_(cn));
    }
    bar_arrive(&g_cnt); bar_wait(&g_cnt, 2u * NCTA);

    for (int t = 0; t < Tlen; ++t) {
        const int p = t & 1, nx = p ^ 1;
        const __half* h0p = g_h0[p];
        const __half* h1p = g_h1[p];

        // output operand prefetch: h1(t-1) lives at parity p
        unsigned long long hpref = 0ull;
        if (tid < 128) {
            int bb = u0 + (tid >> 6), kq = tid & 63;
            hpref = *(const unsigned long long*)(h1p + bb * Hdim + 4 * kq);
        }

        // ---- stage h0 slice into Bs; prefetch h1 slice into registers ----
        uint4 r[8], s[8];
        #pragma unroll
        for (int it = 0; it < 8; ++it)
            r[it] = __ldcg((const uint4*)(h0p + (16 * warp + it) * Hdim) + lane);
        #pragma unroll
        for (int it = 0; it < 8; ++it)
            s[it] = __ldcg((const uint4*)(h0p + (16 * warp + 8 + it) * Hdim) + lane);
        #pragma unroll
        for (int it = 0; it < 8; ++it)
            *((uint4*)(BsW + it * ROWB) + lane) = r[it];
        #pragma unroll
        for (int it = 0; it < 8; ++it)
            r[it] = __ldcg((const uint4*)(h1p + (16 * warp + it) * Hdim) + lane);
        #pragma unroll
        for (int it = 0; it < 8; ++it)
            *((uint4*)(BsW + (8 + it) * ROWB) + lane) = s[it];
        #pragma unroll
        for (int it = 0; it < 8; ++it)
            s[it] = __ldcg((const uint4*)(h1p + (16 * warp + 8 + it) * Hdim) + lane);
        __syncwarp();

        // ---- pass A: [Whh0; Wih1] @ h0(t) ----
        float da0[4] = {0.f, 0.f, 0.f, 0.f};
        float da1[4] = {0.f, 0.f, 0.f, 0.f};
        #pragma unroll
        for (int kt = 0; kt < 16; ++kt) {
            unsigned A0, A1, A2, A3, B0, B1, B2, B3;
            ldm_x4(a0_u + a_row * ROWB + (kt * 16 + a_kh) * 2, A0, A1, A2, A3);
            ldm_x4(bs_u + b_row * ROWB + (kt * 16 + b_kh) * 2, B0, B1, B2, B3);
            mma16816(da0, A0, A1, A2, A3, B0, B1);
            mma16816(da1, A0, A1, A2, A3, B2, B3);
        }
        // L1 partial (rows 8-15 of pass A) becomes C of pass B rows 0-7
        float db0[4] = {da0[2], da0[3], 0.f, 0.f};
        float db1[4] = {da1[2], da1[3], 0.f, 0.f};

        __syncwarp();                         // pass-A ldmatrix reads done
        #pragma unroll
        for (int it = 0; it < 8; ++it)
            *((uint4*)(BsW + it * ROWB) + lane) = r[it];
        #pragma unroll
        for (int it = 0; it < 8; ++it)
            *((uint4*)(BsW + (8 + it) * ROWB) + lane) = s[it];
        __syncwarp();

        // ---- pass B: [Whh1; 0] @ h1(t-1), accumulating L1 gates ----
        #pragma unroll
        for (int kt = 0; kt < 16; ++kt) {
            unsigned A0, A1, A2, A3, B0, B1, B2, B3;
            ldm_x4(a1_u + a_row * ROWB + (kt * 16 + a_kh) * 2, A0, A1, A2, A3);
            ldm_x4(bs_u + b_row * ROWB + (kt * 16 + b_kh) * 2, B0, B1, B2, B3);
            mma16816(db0, A0, A1, A2, A3, B0, B1);
            mma16816(db1, A0, A1, A2, A3, B2, B3);
        }

        // ---- scatter gates to smem ----
        {
            int g8 = lane >> 2;
            int nb = 16 * warp + 2 * (lane & 3);
            *(float2*)&sG[g8 * 260 + nb]           = make_float2(da0[0], da0[1]);
            *(float2*)&sG[g8 * 260 + nb + 8]       = make_float2(da1[0], da1[1]);
            *(float2*)&sG[(8 + g8) * 260 + nb]     = make_float2(db0[0], db0[1]);
            *(float2*)&sG[(8 + g8) * 260 + nb + 8] = make_float2(db1[0], db1[1]);
        }
        __syncthreads();

        // ---- activations (fp32 cell state, fp16 h publish) ----
        {   // layer 1: h1(t)
            float gi = sG[(8 + 0*2 + jmu) * 260 + bown] + sB1[0*2 + jmu];
            float gf = sG[(8 + 1*2 + jmu) * 260 + bown] + sB1[1*2 + jmu];
            float gg = sG[(8 + 2*2 + jmu) * 260 + bown] + sB1[2*2 + jmu];
            float go = sG[(8 + 3*2 + jmu) * 260 + bown] + sB1[3*2 + jmu];
            float cn = sigf(gf) * c1 + sigf(gi) * tanhf_(gg);
            c1 = cn;
            g_h1[nx][bown * Hdim + u0 + jmu] = __float2half(sigf(go) * tanhf_(cn));
        }
        if (t < Tlen - 1) {  // layer 0: h0(t+1)
            float xv = g_xT[(t + 1) * Bsz + bown];
            float gi = sG[(0*2 + jmu) * 260 + bown] + fmaf(sWx[0*2 + jmu], xv, sB0[0*2 + jmu]);
            float gf = sG[(1*2 + jmu) * 260 + bown] + fmaf(sWx[1*2 + jmu], xv, sB0[1*2 + jmu]);
            float gg = sG[(2*2 + jmu) * 260 + bown] + fmaf(sWx[2*2 + jmu], xv, sB0[2*2 + jmu]);
            float go = sG[(3*2 + jmu) * 260 + bown] + fmaf(sWx[3*2 + jmu], xv, sB0[3*2 + jmu]);
            float cn = sigf(gf) * c0 + sigf(gi) * tanhf_(gg);
            c0 = cn;
            g_h0[nx][bown * Hdim + u0 + jmu] = __float2half(sigf(go) * tanhf_(cn));
        }

        bar_arrive(&g_cnt);                  // output runs in the wait shadow

        if (t >= 1) {
            if (tid < 128) {
                int kq = tid & 63;
                unsigned lo_u = (unsigned)hpref;
                unsigned hi_u = (unsigned)(hpref >> 32);
                float2 lo = __half22float2(*(__half2*)&lo_u);
                float2 hi = __half22float2(*(__half2*)&hi_u);
                float4 wl = sW4[kq];
                float part = lo.x * wl.x + lo.y * wl.y + hi.x * wl.z + hi.y * wl.w;
                #pragma unroll
                for (int off = 16; off > 0; off >>= 1)
                    part += __shfl_down_sync(0xffffffffu, part, off);
                if ((tid & 31) == 0) sOut[tid >> 5] = part;
            }
            __syncthreads();
            if (tid == 0) {
                out[(u0 + 0) * Tlen + (t - 1)] = sOut[0] + sOut[1] + bl;
                out[(u0 + 1) * Tlen + (t - 1)] = sOut[2] + sOut[3] + bl;
            }
        }

        bar_wait(&g_cnt, (unsigned)(t + 3) * NCTA);
    }

    // ---- final output(1023): h1(1023) at parity 0 ----
    {
        if (tid < 128) {
            int bb = u0 + (tid >> 6), kq = tid & 63;
            unsigned long long hv =
                *(const unsigned long long*)(g_h1[0] + bb * Hdim + 4 * kq);
            unsigned lo_u = (unsigned)hv, hi_u = (unsigned)(hv >> 32);
            float2 lo = __half22float2(*(__half2*)&lo_u);
            float2 hi = __half22float2(*(__half2*)&hi_u);
            float4 wl = sW4[kq];
            float part = lo.x * wl.x + lo.y * wl.y + hi.x * wl.z + hi.y * wl.w;
            #pragma unroll
            for (int off = 16; off > 0; off >>= 1)
                part += __shfl_down_sync(0xffffffffu, part, off);
            if ((tid & 31) == 0) sOut[tid >> 5] = part;
        }
        __syncthreads();
        if (tid == 0) {
            out[(u0 + 0) * Tlen + (Tlen - 1)] = sOut[0] + sOut[1] + bl;
            out[(u0 + 1) * Tlen + (Tlen - 1)] = sOut[2] + sOut[3] + bl;
        }
    }

    // reset counters for next launch
    __syncthreads();
    if (tid == 0) {
        __threadfence();
        unsigned old = atomicAdd(&g_done, 1u);
        if (old == NCTA - 1) {
            atomicExch(&g_cnt, 0u);
            atomicExch(&g_done, 0u);
        }
    }
}

extern "C" void kernel_launch(void* const* d_in, const int* in_sizes, int n_in,
                              void* d_out, int out_size) {
    (void)in_sizes; (void)n_in; (void)out_size;
    cudaFuncSetAttribute(lstm_mma, cudaFuncAttributeMaxDynamicSharedMemorySize,
                         DYN_SMEM);
    lstm_mma<<<NCTA, NTH, DYN_SMEM>>>(
        (const float*)d_in[0],
        (const float*)d_in[1], (const float*)d_in[2],
        (const float*)d_in[3], (const float*)d_in[4],
        (const float*)d_in[5], (const float*)d_in[6],
        (const float*)d_in[7], (const float*)d_in[8],
        (const float*)d_in[9], (const float*)d_in[10],
        (float*)d_out);
}

// round 16
// speedup vs baseline: 4.6039x; 1.8033x over previous
#include <cuda_runtime.h>
#include <cuda_fp16.h>
#include <math.h>

#define NCTA 128
#define NTH  512
#define Bsz  256
#define Tlen 1024
#define Hdim 256

#define ROWB 528                        // 264 halfs per smem row
#define OFF_S0 0                        // h0 slab: 32 rows
#define OFF_S1 16896                    // h1 slab: 32 rows
#define OFF_W1 33792                    // Whh1 fp16 [n=64][k=256] rows 264
#define DYN_SMEM (33792 + 64 * ROWB)    // 67584 B

// Persistent h state, fp16, layout [b][k], double-buffered by parity.
// Parity p holds (h0(t), h1(t-1)) for t with t&1 == p.
__device__ __half g_h0[2][Bsz * Hdim];
__device__ __half g_h1[2][Bsz * Hdim];
__device__ float g_xT[Tlen * Bsz];
__device__ unsigned g_cnt = 0, g_done = 0;

__device__ __forceinline__ float sigf(float x) {
    return __fdividef(1.0f, 1.0f + __expf(-x));
}
__device__ __forceinline__ float tanhf_(float x) {
    return fmaf(2.0f, sigf(2.0f * x), -1.0f);
}
__device__ __forceinline__ unsigned smem_u32(const void* p) {
    unsigned a;
    asm("{ .reg .u64 t; cvta.to.shared.u64 t, %1; cvt.u32.u64 %0, t; }"
        : "=r"(a) : "l"(p));
    return a;
}
__device__ __forceinline__ unsigned packh2(float a, float b) {
    __half2 h = __floats2half2_rn(a, b);
    return *reinterpret_cast<unsigned*>(&h);
}
__device__ __forceinline__ void ldm_x4(unsigned addr, unsigned& r0, unsigned& r1,
                                       unsigned& r2, unsigned& r3) {
    asm volatile("ldmatrix.sync.aligned.m8n8.x4.shared.b16 {%0,%1,%2,%3}, [%4];"
                 : "=r"(r0), "=r"(r1), "=r"(r2), "=r"(r3) : "r"(addr) : "memory");
}
__device__ __forceinline__ void mma16816(float* d, unsigned a0, unsigned a1,
                                         unsigned a2, unsigned a3,
                                         unsigned b0, unsigned b1) {
    asm volatile("mma.sync.aligned.m16n8k16.row.col.f32.f16.f16.f32 "
                 "{%0,%1,%2,%3}, {%4,%5,%6,%7}, {%8,%9}, {%0,%1,%2,%3};"
                 : "+f"(d[0]), "+f"(d[1]), "+f"(d[2]), "+f"(d[3])
                 : "r"(a0), "r"(a1), "r"(a2), "r"(a3), "r"(b0), "r"(b1));
}

// Split-phase grid barrier (NCTA co-resident CTAs, 1/SM).
__device__ __forceinline__ void bar_arrive(unsigned* c) {
    __syncthreads();
    if (threadIdx.x == 0) {
        asm volatile("red.release.gpu.global.add.u32 [%0], %1;"
                     :: "l"(c), "r"(1u) : "memory");
    }
}
__device__ __forceinline__ void bar_wait(unsigned* c, unsigned target) {
    if (threadIdx.x == 0) {
        unsigned v;
        do {
            asm volatile("ld.acquire.gpu.u32 %0, [%1];" : "=r"(v) : "l"(c));
        } while (v < target);
    }
    __syncthreads();
}

__global__ void __launch_bounds__(NTH, 1)
lstm_mma2(const float* __restrict__ x,
          const float* __restrict__ Wih0, const float* __restrict__ Whh0,
          const float* __restrict__ bih0, const float* __restrict__ bhh0,
          const float* __restrict__ Wih1, const float* __restrict__ Whh1,
          const float* __restrict__ bih1, const float* __restrict__ bhh1,
          const float* __restrict__ Wlin, const float* __restrict__ blin,
          float* __restrict__ out)
{
    extern __shared__ char dsm[];
    __shared__ float  sG[32 * 136];      // gates [batch][col]; cols 0-63 L0, 64-127 L1
    __shared__ float4 sW4[64];           // Wlin quads
    __shared__ float  sWx[64], sB0[64], sB1[64];   // per gate col = q*16+uloc
    __shared__ float  sOut[4];

    const int tid = threadIdx.x, lane = tid & 31, warp = tid >> 5;
    const int cta = blockIdx.x;
    const int ug = cta >> 3, bg = cta & 7;   // 16 unit-groups x 8 batch-groups
    const int ub = 16 * ug, bb = 32 * bg;
    const int mt = warp >> 3;                // batch-row tile 0/1
    const int n0 = (warp & 7) * 8;           // gate-col tile base

    // activation role: 32 batches x 16 units
    const int bloc = tid >> 4, ul = tid & 15;
    const int gb = bb + bloc, gu = ub + ul;

    // fragment lane mapping (m16n8k16)
    const int fr = lane >> 2;                // 0..7
    const int fc = (lane & 3) * 2;           // k offset within tile
    const int nmy = n0 + fr;                 // my gate col 0..63
    const int grow = (nmy >> 4) * 256 + ub + (nmy & 15);  // global gate row

    // output-gather role (tid < 128): CTA emits batches {2cta, 2cta+1}
    const int ob = 2 * cta + (tid >> 6);
    const int okq = tid & 63;

    // ---- one-time staging ----
    for (int i = cta * NTH + tid; i < Bsz * Tlen; i += NCTA * NTH) {
        int b = i >> 10, t = i & (Tlen - 1);
        g_xT[t * Bsz + b] = x[i];
    }
    for (int e = tid; e < 64 * 256; e += NTH) {      // Whh1 fp16 [n][k]
        int n = e >> 8, k = e & 255;
        int gr = (n >> 4) * 256 + ub + (n & 15);
        ((__half*)(dsm + OFF_W1))[n * 264 + k] = __float2half(Whh1[gr * 256 + k]);
    }
    if (tid < 64) {
        int gr = (tid >> 4) * 256 + ub + (tid & 15);
        sWx[tid] = Wih0[gr];
        sB0[tid] = bih0[gr] + bhh0[gr];
        sB1[tid] = bih1[gr] + bhh1[gr];
        sW4[tid] = ((const float4*)Wlin)[tid];
    }
    const float bl = __ldg(blin);

    // weight B-fragments in registers (loaded once, fp32->fp16)
    unsigned w0f[16][2], wif[16][2];
    {
        const float* r0 = Whh0 + grow * 256;
        const float* r1 = Wih1 + grow * 256;
        #pragma unroll
        for (int kt = 0; kt < 16; ++kt) {
            int k = kt * 16 + fc;
            w0f[kt][0] = packh2(r0[k],     r0[k + 1]);
            w0f[kt][1] = packh2(r0[k + 8], r0[k + 9]);
            wif[kt][0] = packh2(r1[k],     r1[k + 1]);
            wif[kt][1] = packh2(r1[k + 8], r1[k + 9]);
        }
    }

    g_h1[0][gb * Hdim + gu] = __float2half(0.0f);    // h1(-1) = 0
    float c0 = 0.f, c1 = 0.f;

    bar_arrive(&g_cnt); bar_wait(&g_cnt, 1u * NCTA);

    // ---- prologue: h0(0) from zero state ----
    {
        float xv = g_xT[gb];
        float gi = fmaf(sWx[0*16 + ul], xv, sB0[0*16 + ul]);
        float gg = fmaf(sWx[2*16 + ul], xv, sB0[2*16 + ul]);
        float go = fmaf(sWx[3*16 + ul], xv, sB0[3*16 + ul]);
        float cn = sigf(gi) * tanhf_(gg);
        c0 = cn;
        g_h0[0][gb * Hdim + gu] = __float2half(sigf(go) * tanhf_(cn));
    }
    bar_arrive(&g_cnt); bar_wait(&g_cnt, 2u * NCTA);

    const unsigned sb = smem_u32(dsm);
    // ldmatrix A base: lanes 0-15 -> rows, lanes 16-31 -> rows at k+8
    const unsigned aL = sb + (mt * 16 + (lane & 15)) * ROWB + ((lane >> 4) & 1) * 16;
    const char* w1p = dsm + OFF_W1 + nmy * ROWB + fc * 2;

    for (int t = 0; t < Tlen; ++t) {
        const int p = t & 1, nx = p ^ 1;
        const __half* h0p = g_h0[p];
        const __half* h1p = g_h1[p];

        // output operand prefetch: h1(t-1) at parity p
        unsigned long long hpref = 0ull;
        if (tid < 128)
            hpref = *(const unsigned long long*)(h1p + ob * Hdim + 4 * okq);

        // ---- stage h slabs (32 batches x 256 k, both layers) ----
        for (int idx = tid; idx < 2048; idx += NTH) {
            int sl = idx >> 10, rr = (idx >> 5) & 31, c16 = idx & 31;
            const __half* src = (sl ? h1p : h0p) + (bb + rr) * Hdim + c16 * 8;
            uint4 v = __ldcg((const uint4*)src);
            *(uint4*)(dsm + (sl ? OFF_S1 : OFF_S0) + rr * ROWB + c16 * 16) = v;
        }
        __syncthreads();

        // ---- MMA: d0 = L0 gates (Whh0@h0), d1 = L1 gates (Wih1@h0 + Whh1@h1) ----
        float d0[4] = {0.f, 0.f, 0.f, 0.f};
        float d1[4] = {0.f, 0.f, 0.f, 0.f};
        #pragma unroll
        for (int kt = 0; kt < 16; ++kt) {
            unsigned A0, A1, A2, A3;
            ldm_x4(aL + OFF_S0 + kt * 32, A0, A1, A2, A3);
            mma16816(d0, A0, A1, A2, A3, w0f[kt][0], w0f[kt][1]);
            mma16816(d1, A0, A1, A2, A3, wif[kt][0], wif[kt][1]);
        }
        #pragma unroll
        for (int kt = 0; kt < 16; ++kt) {
            unsigned A0, A1, A2, A3;
            ldm_x4(aL + OFF_S1 + kt * 32, A0, A1, A2, A3);
            unsigned b0 = *(const unsigned*)(w1p + kt * 32);
            unsigned b1 = *(const unsigned*)(w1p + kt * 32 + 16);
            mma16816(d1, A0, A1, A2, A3, b0, b1);
        }

        // ---- scatter gates to sG[batch][col] ----
        {
            int r = mt * 16 + fr, c = n0 + fc;
            *(float2*)&sG[r * 136 + c]            = make_float2(d0[0], d0[1]);
            *(float2*)&sG[(r + 8) * 136 + c]      = make_float2(d0[2], d0[3]);
            *(float2*)&sG[r * 136 + 64 + c]       = make_float2(d1[0], d1[1]);
            *(float2*)&sG[(r + 8) * 136 + 64 + c] = make_float2(d1[2], d1[3]);
        }
        __syncthreads();

        // ---- activations (fp32 cell state, fp16 h publish) ----
        {   // layer 1: h1(t)
            float gi = sG[bloc * 136 + 64 + 0*16 + ul] + sB1[0*16 + ul];
            float gf = sG[bloc * 136 + 64 + 1*16 + ul] + sB1[1*16 + ul];
            float gg = sG[bloc * 136 + 64 + 2*16 + ul] + sB1[2*16 + ul];
            float go = sG[bloc * 136 + 64 + 3*16 + ul] + sB1[3*16 + ul];
            float cn = sigf(gf) * c1 + sigf(gi) * tanhf_(gg);
            c1 = cn;
            g_h1[nx][gb * Hdim + gu] = __float2half(sigf(go) * tanhf_(cn));
        }
        if (t < Tlen - 1) {  // layer 0: h0(t+1)
            float xv = g_xT[(t + 1) * Bsz + gb];
            float gi = sG[bloc * 136 + 0*16 + ul] + fmaf(sWx[0*16 + ul], xv, sB0[0*16 + ul]);
            float gf = sG[bloc * 136 + 1*16 + ul] + fmaf(sWx[1*16 + ul], xv, sB0[1*16 + ul]);
            float gg = sG[bloc * 136 + 2*16 + ul] + fmaf(sWx[2*16 + ul], xv, sB0[2*16 + ul]);
            float go = sG[bloc * 136 + 3*16 + ul] + fmaf(sWx[3*16 + ul], xv, sB0[3*16 + ul]);
            float cn = sigf(gf) * c0 + sigf(gi) * tanhf_(gg);
            c0 = cn;
            g_h0[nx][gb * Hdim + gu] = __float2half(sigf(go) * tanhf_(cn));
        }

        bar_arrive(&g_cnt);                  // output runs in the wait shadow

        if (t >= 1) {
            if (tid < 128) {
                unsigned lo_u = (unsigned)hpref, hi_u = (unsigned)(hpref >> 32);
                float2 lo = __half22float2(*(__half2*)&lo_u);
                float2 hi = __half22float2(*(__half2*)&hi_u);
                float4 wl = sW4[okq];
                float part = lo.x * wl.x + lo.y * wl.y + hi.x * wl.z + hi.y * wl.w;
                #pragma unroll
                for (int off = 16; off > 0; off >>= 1)
                    part += __shfl_down_sync(0xffffffffu, part, off);
                if ((tid & 31) == 0) sOut[tid >> 5] = part;
            }
            __syncthreads();
            if (tid == 0) {
                out[(2 * cta + 0) * Tlen + (t - 1)] = sOut[0] + sOut[1] + bl;
                out[(2 * cta + 1) * Tlen + (t - 1)] = sOut[2] + sOut[3] + bl;
            }
        }

        bar_wait(&g_cnt, (unsigned)(t + 3) * NCTA);
    }

    // ---- final output(1023): h1(1023) at parity 0 ----
    {
        if (tid < 128) {
            unsigned long long hv =
                *(const unsigned long long*)(g_h1[0] + ob * Hdim + 4 * okq);
            unsigned lo_u = (unsigned)hv, hi_u = (unsigned)(hv >> 32);
            float2 lo = __half22float2(*(__half2*)&lo_u);
            float2 hi = __half22float2(*(__half2*)&hi_u);
            float4 wl = sW4[okq];
            float part = lo.x * wl.x + lo.y * wl.y + hi.x * wl.z + hi.y * wl.w;
            #pragma unroll
            for (int off = 16; off > 0; off >>= 1)
                part += __shfl_down_sync(0xffffffffu, part, off);
            if ((tid & 31) == 0) sOut[tid >> 5] = part;
        }
        __syncthreads();
        if (tid == 0) {
            out[(2 * cta + 0) * Tlen + (Tlen - 1)] = sOut[0] + sOut[1] + bl;
            out[(2 * cta + 1) * Tlen + (Tlen - 1)] = sOut[2] + sOut[3] + bl;
        }
    }

    // reset counters for next launch
    __syncthreads();
    if (tid == 0) {
        __threadfence();
        unsigned old = atomicAdd(&g_done, 1u);
        if (old == NCTA - 1) {
            atomicExch(&g_cnt, 0u);
            atomicExch(&g_done, 0u);
        }
    }
}

extern "C" void kernel_launch(void* const* d_in, const int* in_sizes, int n_in,
                              void* d_out, int out_size) {
    (void)in_sizes; (void)n_in; (void)out_size;
    cudaFuncSetAttribute(lstm_mma2, cudaFuncAttributeMaxDynamicSharedMemorySize,
                         DYN_SMEM);
    lstm_mma2<<<NCTA, NTH, DYN_SMEM>>>(
        (const float*)d_in[0],
        (const float*)d_in[1], (const float*)d_in[2],
        (const float*)d_in[3], (const float*)d_in[4],
        (const float*)d_in[5], (const float*)d_in[6],
        (const float*)d_in[7], (const float*)d_in[8],
        (const float*)d_in[9], (const float*)d_in[10],
        (float*)d_out);
}